// round 12
// baseline (speedup 1.0000x reference)
#include <cuda_runtime.h>

#define BINS 10
#define TPB  256
#define BPSM 4
#define GRID (152 * BPSM)   // one wave on GB300 (152 SMs)

// Global scratch (allocation-free __device__ globals, zero-init at load;
// last block re-zeros them each run so graph replays stay deterministic).
__device__ double       g_cnt[BINS];
__device__ double       g_sum[BINS];
__device__ unsigned int g_done;

__device__ __forceinline__ float rcp_fast(float x) { float r; asm("rcp.approx.f32 %0, %1;" : "=f"(r) : "f"(x)); return r; }
__device__ __forceinline__ float lg2_fast(float x) { float r; asm("lg2.approx.f32 %0, %1;" : "=f"(r) : "f"(x)); return r; }
__device__ __forceinline__ float ex2_fast(float x) { float r; asm("ex2.approx.f32 %0, %1;" : "=f"(r) : "f"(x)); return r; }

__device__ __forceinline__ unsigned smem_off(const void* p)
{
    unsigned a;
    asm("{ .reg .u64 t; cvta.to.shared.u64 t, %1; cvt.u32.u64 %0, t; }"
        : "=r"(a) : "l"(p));
    return a;
}

__global__ void __launch_bounds__(TPB, BPSM)
ghm_fused(const float4* __restrict__ x4,
          const int2*   __restrict__ t2,
          int npairs, int nrows,
          const float* __restrict__ xs,
          const int*   __restrict__ ts,
          float* __restrict__ out)
{
    // TWO privatized histograms (elements 0,1 -> copy0; 2,3 -> copy1).
    // Within a copy the two RMWs are ordered in the asm (collision-safe);
    // across copies they are independent (overlapped LDS latency).
    // Address = hbase + bin*2048, hbase = base + tid*8 -> bank = tid.
    __shared__ float2 hist[2][BINS][TPB];
    __shared__ int    s_last;
    const int tid = threadIdx.x;
#pragma unroll
    for (int b = 0; b < BINS; b++) {
        hist[0][b][tid] = make_float2(0.0f, 0.0f);
        hist[1][b][tid] = make_float2(0.0f, 0.0f);
    }
    __syncthreads();

    const unsigned hb0 = smem_off(&hist[0][0][tid]);
    const unsigned hb1 = hb0 + BINS * TPB * 8;

    // Hand-written PTX body: ~80 ops / 4 elements (~20/elem) vs the ~43/elem
    // the compiler emits from C. Per elem:
    //   s=x^mask; e=exp(-|x|); d=1+e; u=9.9999*rcp(d);
    //   us=(s>=0)?u:9.9999-u; bin=trunc(us); bce=(s>=0?|x|:0)+ln2*lg2(d)
    // RMW adds are packed f32x2 (count+=1 and sum+=bce in ONE instruction).
    // Constants: 0fBFB8AA3B=-log2e, 0f3F800000=1.0, 0f411FFF97=9.9999, 0f3F317218=ln2
    const int stride = GRID * TPB;
    for (int i = blockIdx.x * TPB + tid; i < npairs; i += stride) {
        float4 xv = x4[i];   // rows 2i (x,y) and 2i+1 (z,w)
        int2   tv = t2[i];

        asm volatile(
            "{\n\t"
            ".reg .f32 a0,a1,a2,a3,w0,w1,w2,w3,e0,e1,e2,e3,d0,d1,d2,d3;\n\t"
            ".reg .f32 r0,r1,r2,r3,u0,u1,u2,u3,v0,v1,v2,v3,q0,q1,q2,q3;\n\t"
            ".reg .f32 g0,g1,g2,g3,l0,l1,l2,l3,c0,c1,c2,c3,one;\n\t"
            ".reg .b32 m0,m1,m2,m3,s0,s1,s2,s3,b0,b1,b2,b3,o0,o1,o2,o3;\n\t"
            ".reg .b64 h0,h1,h2,h3,k0,k1,k2,k3;\n\t"
            ".reg .pred p0,p1,p2,p3;\n\t"
            // row masks: class1 = t<<31, class0 = class1 ^ signbit
            "shl.b32 m1, %4, 31;\n\t"
            "xor.b32 m0, m1, 0x80000000;\n\t"
            "shl.b32 m3, %5, 31;\n\t"
            "xor.b32 m2, m3, 0x80000000;\n\t"
            // signed views s_i = x_i ^ m_i
            "mov.b32 s0, %0;  xor.b32 s0, s0, m0;\n\t"
            "mov.b32 s1, %1;  xor.b32 s1, s1, m1;\n\t"
            "mov.b32 s2, %2;  xor.b32 s2, s2, m2;\n\t"
            "mov.b32 s3, %3;  xor.b32 s3, s3, m3;\n\t"
            // e = exp(-|x|)
            "abs.f32 a0, %0;  abs.f32 a1, %1;  abs.f32 a2, %2;  abs.f32 a3, %3;\n\t"
            "mul.f32 w0, a0, 0fBFB8AA3B;\n\t"
            "mul.f32 w1, a1, 0fBFB8AA3B;\n\t"
            "mul.f32 w2, a2, 0fBFB8AA3B;\n\t"
            "mul.f32 w3, a3, 0fBFB8AA3B;\n\t"
            "ex2.approx.f32 e0, w0;\n\t"
            "ex2.approx.f32 e1, w1;\n\t"
            "ex2.approx.f32 e2, w2;\n\t"
            "ex2.approx.f32 e3, w3;\n\t"
            // d = 1+e; u = 9.9999*rcp(d); v = 9.9999-u
            "add.f32 d0, e0, 0f3F800000;\n\t"
            "add.f32 d1, e1, 0f3F800000;\n\t"
            "add.f32 d2, e2, 0f3F800000;\n\t"
            "add.f32 d3, e3, 0f3F800000;\n\t"
            "rcp.approx.f32 r0, d0;\n\t"
            "rcp.approx.f32 r1, d1;\n\t"
            "rcp.approx.f32 r2, d2;\n\t"
            "rcp.approx.f32 r3, d3;\n\t"
            "mul.f32 u0, r0, 0f411FFF97;\n\t"
            "mul.f32 u1, r1, 0f411FFF97;\n\t"
            "mul.f32 u2, r2, 0f411FFF97;\n\t"
            "mul.f32 u3, r3, 0f411FFF97;\n\t"
            "sub.f32 v0, 0f411FFF97, u0;\n\t"
            "sub.f32 v1, 0f411FFF97, u1;\n\t"
            "sub.f32 v2, 0f411FFF97, u2;\n\t"
            "sub.f32 v3, 0f411FFF97, u3;\n\t"
            // sign select -> bin, and max(s,0)
            "setp.ge.s32 p0, s0, 0;\n\t"
            "setp.ge.s32 p1, s1, 0;\n\t"
            "setp.ge.s32 p2, s2, 0;\n\t"
            "setp.ge.s32 p3, s3, 0;\n\t"
            "selp.f32 q0, u0, v0, p0;\n\t"
            "selp.f32 q1, u1, v1, p1;\n\t"
            "selp.f32 q2, u2, v2, p2;\n\t"
            "selp.f32 q3, u3, v3, p3;\n\t"
            "cvt.rzi.s32.f32 b0, q0;\n\t"
            "cvt.rzi.s32.f32 b1, q1;\n\t"
            "cvt.rzi.s32.f32 b2, q2;\n\t"
            "cvt.rzi.s32.f32 b3, q3;\n\t"
            "selp.f32 g0, a0, 0f00000000, p0;\n\t"
            "selp.f32 g1, a1, 0f00000000, p1;\n\t"
            "selp.f32 g2, a2, 0f00000000, p2;\n\t"
            "selp.f32 g3, a3, 0f00000000, p3;\n\t"
            // bce = g + ln2*lg2(d)
            "lg2.approx.f32 l0, d0;\n\t"
            "lg2.approx.f32 l1, d1;\n\t"
            "lg2.approx.f32 l2, d2;\n\t"
            "lg2.approx.f32 l3, d3;\n\t"
            "fma.rn.f32 c0, l0, 0f3F317218, g0;\n\t"
            "fma.rn.f32 c1, l1, 0f3F317218, g1;\n\t"
            "fma.rn.f32 c2, l2, 0f3F317218, g2;\n\t"
            "fma.rn.f32 c3, l3, 0f3F317218, g3;\n\t"
            // offsets: elems 0,1 -> copy0 (%6); elems 2,3 -> copy1 (%7)
            "mad.lo.s32 o0, b0, 2048, %6;\n\t"
            "mad.lo.s32 o1, b1, 2048, %6;\n\t"
            "mad.lo.s32 o2, b2, 2048, %7;\n\t"
            "mad.lo.s32 o3, b3, 2048, %7;\n\t"
            "mov.f32 one, 0f3F800000;\n\t"
            "mov.b64 k0, {one, c0};\n\t"
            "mov.b64 k1, {one, c1};\n\t"
            "mov.b64 k2, {one, c2};\n\t"
            "mov.b64 k3, {one, c3};\n\t"
            // copy0 chain (ordered: o0 may equal o1) and copy1 chain run
            // interleaved -> two overlapped LDS latency windows.
            "ld.shared.b64 h0, [o0];\n\t"
            "ld.shared.b64 h2, [o2];\n\t"
            "add.rn.f32x2 h0, h0, k0;\n\t"
            "add.rn.f32x2 h2, h2, k2;\n\t"
            "st.shared.b64 [o0], h0;\n\t"
            "st.shared.b64 [o2], h2;\n\t"
            "ld.shared.b64 h1, [o1];\n\t"
            "ld.shared.b64 h3, [o3];\n\t"
            "add.rn.f32x2 h1, h1, k1;\n\t"
            "add.rn.f32x2 h3, h3, k3;\n\t"
            "st.shared.b64 [o1], h1;\n\t"
            "st.shared.b64 [o3], h3;\n\t"
            "}\n\t"
            :: "f"(xv.x), "f"(xv.y), "f"(xv.z), "f"(xv.w),
               "r"(tv.x), "r"(tv.y), "r"(hb0), "r"(hb1)
            : "memory");
    }

    // Tail row (nrows odd): block 0 only, direct double atomics.
    if (blockIdx.x == 0 && tid == 0 && (nrows & 1)) {
        int rowi = nrows - 1;
        int t = ts[rowi];
        for (int c = 0; c < 2; c++) {
            float x = xs[rowi * 2 + c];
            unsigned mask = ((t == c) ? 0x80000000u : 0u);
            int   sx = __float_as_int(x) ^ (int)mask;
            float ax = fabsf(x);
            float e  = ex2_fast(ax * -1.4426950408889634f);
            float d  = 1.0f + e;
            float u  = rcp_fast(d) * 9.9999f;
            bool pos = (sx >= 0);
            float us = pos ? u : (9.9999f - u);
            int  bin = (int)us;
            float m  = pos ? ax : 0.0f;
            float bce = fmaf(lg2_fast(d), 0.69314718055994531f, m);
            atomicAdd(&g_cnt[bin], 1.0);
            atomicAdd(&g_sum[bin], (double)bce);
        }
    }
    __syncthreads();

    // Fold copy1 into copy0, then tree-reduce 256 columns x 10 bins.
#pragma unroll
    for (int b = 0; b < BINS; b++) {
        float2 a = hist[0][b][tid];
        float2 c = hist[1][b][tid];
        hist[0][b][tid] = make_float2(a.x + c.x, a.y + c.y);
    }
    __syncthreads();
    for (int off = TPB / 2; off > 0; off >>= 1) {
        if (tid < off) {
#pragma unroll
            for (int b = 0; b < BINS; b++) {
                float2 a = hist[0][b][tid];
                float2 c = hist[0][b][tid + off];
                hist[0][b][tid] = make_float2(a.x + c.x, a.y + c.y);
            }
        }
        __syncthreads();
    }

    if (tid < BINS) {
        atomicAdd(&g_cnt[tid], (double)hist[0][tid][0].x);
        atomicAdd(&g_sum[tid], (double)hist[0][tid][0].y);
    }
    __syncthreads();

    // Last-block finalize (and reset for the next graph replay).
    if (tid == 0) {
        __threadfence();
        unsigned old = atomicAdd(&g_done, 1u);
        s_last = (old == GRID - 1) ? 1 : 0;
    }
    __syncthreads();

    if (s_last && tid == 0) {
        __threadfence();
        volatile double* vc = g_cnt;
        volatile double* vs = g_sum;
        double cnt[BINS], sum[BINS];
        double nonempty = 0.0;
        for (int b = 0; b < BINS; b++) {
            cnt[b] = vc[b];
            sum[b] = vs[b];
            if (cnt[b] > 0.0) nonempty += 1.0;
        }
        // mean(weight*bce) = (1/N) * sum_b (N/gd_b) * S_b = sum_b S_b / gd_b
        double loss = 0.0;
        for (int b = 0; b < BINS; b++) {
            double gd = cnt[b] * nonempty;
            if (gd < 1e-4) gd = 1e-4;
            loss += sum[b] / gd;
        }
        out[0] = (float)loss;
        for (int b = 0; b < BINS; b++) { vc[b] = 0.0; vs[b] = 0.0; }
        __threadfence();
        g_done = 0u;
    }
}

extern "C" void kernel_launch(void* const* d_in, const int* in_sizes, int n_in,
                              void* d_out, int out_size)
{
    // x: [B,2] float32 (2B elems), target: [B] int32 (B elems) — identify by count.
    const float* x;
    const int*   t;
    int nrows;
    if (in_sizes[0] >= 2 * in_sizes[1]) {
        x = (const float*)d_in[0];
        t = (const int*)d_in[1];
        nrows = in_sizes[1];
    } else {
        x = (const float*)d_in[1];
        t = (const int*)d_in[0];
        nrows = in_sizes[0];
    }
    int npairs = nrows >> 1;   // 2 rows (4 elements) per iteration

    ghm_fused<<<GRID, TPB>>>((const float4*)x, (const int2*)t, npairs, nrows,
                             x, t, (float*)d_out);
}

// round 13
// speedup vs baseline: 1.2617x; 1.2617x over previous
#include <cuda_runtime.h>

#define BINS 10
#define TPB  256
#define BPSM 8
#define GRID (152 * BPSM)   // 8 blocks/SM -> 64 warps/SM (100% occupancy target)

// Global scratch (allocation-free __device__ globals, zero-init at load;
// the finalize kernel re-zeros them so graph replays stay deterministic).
__device__ double g_cnt[BINS];
__device__ double g_sum[BINS];

__device__ __forceinline__ float rcp_fast(float x) { float r; asm("rcp.approx.f32 %0, %1;" : "=f"(r) : "f"(x)); return r; }
__device__ __forceinline__ float lg2_fast(float x) { float r; asm("lg2.approx.f32 %0, %1;" : "=f"(r) : "f"(x)); return r; }
__device__ __forceinline__ float ex2_fast(float x) { float r; asm("ex2.approx.f32 %0, %1;" : "=f"(r) : "f"(x)); return r; }

// s = x ^ mask (mask = target-match << 31);  |s| = |x|
//   e = exp(-|x|);  d = 1+e;  u = 9.9999*rcp(d)
//   us = (s>=0) ? u : 9.9999-u;  bin = trunc(us) in [0,9]
//   bce = (s>=0 ? |x| : 0) + ln2*lg2(d)
__device__ __forceinline__ void ghm_elem(float x, unsigned mask, float2 (*hist)[TPB], int tid)
{
    int   sx = __float_as_int(x) ^ (int)mask;
    float ax = fabsf(x);
    float e  = ex2_fast(ax * -1.4426950408889634f);
    float d  = 1.0f + e;
    float u  = rcp_fast(d) * 9.9999f;
    bool pos = (sx >= 0);
    float us = pos ? u : (9.9999f - u);
    int  bin = (int)us;
    float m  = pos ? ax : 0.0f;
    float bce = fmaf(lg2_fast(d), 0.69314718055994531f, m);
    float2 h = hist[bin][tid];
    h.x += 1.0f;
    h.y += bce;
    hist[bin][tid] = h;
}

// MAIN kernel: streaming histogram only. NO threadfence, NO done-counter,
// NO finalize tail — ends at the per-block global atomics.
__global__ void __launch_bounds__(TPB, BPSM)
ghm_main(const float4* __restrict__ x4,
         const int2*   __restrict__ t2,
         int npairs, int nrows,
         const float* __restrict__ xs,
         const int*   __restrict__ ts)
{
    // Single privatized histogram: hist[bin][tid], float2 = (count, bce_sum).
    // Stride 8B -> bank = tid (mod 32): conflict-free for any bin mix.
    __shared__ float2 hist[BINS][TPB];
    const int tid = threadIdx.x;
#pragma unroll
    for (int b = 0; b < BINS; b++) hist[b][tid] = make_float2(0.0f, 0.0f);
    __syncthreads();

    // Simple grid-stride loop: 2 rows (4 elements) per iteration.
    // Latency hiding from 64 warps/SM (R10's best-measured config).
    const int stride = GRID * TPB;
    for (int i = blockIdx.x * TPB + tid; i < npairs; i += stride) {
        float4 xv = x4[i];   // rows 2i (x,y) and 2i+1 (z,w)
        int2   tv = t2[i];

        unsigned m1a = ((unsigned)tv.x) << 31, m0a = m1a ^ 0x80000000u;
        unsigned m1b = ((unsigned)tv.y) << 31, m0b = m1b ^ 0x80000000u;

        ghm_elem(xv.x, m0a, hist, tid);
        ghm_elem(xv.y, m1a, hist, tid);
        ghm_elem(xv.z, m0b, hist, tid);
        ghm_elem(xv.w, m1b, hist, tid);
    }

    // Tail row (nrows odd): one thread, direct double atomics.
    if (blockIdx.x == 0 && tid == 0 && (nrows & 1)) {
        int rowi = nrows - 1;
        int t = ts[rowi];
        for (int c = 0; c < 2; c++) {
            float x = xs[rowi * 2 + c];
            unsigned mask = ((t == c) ? 0x80000000u : 0u);
            int   sx = __float_as_int(x) ^ (int)mask;
            float ax = fabsf(x);
            float e  = ex2_fast(ax * -1.4426950408889634f);
            float d  = 1.0f + e;
            float u  = rcp_fast(d) * 9.9999f;
            bool pos = (sx >= 0);
            float us = pos ? u : (9.9999f - u);
            int  bin = (int)us;
            float m  = pos ? ax : 0.0f;
            float bce = fmaf(lg2_fast(d), 0.69314718055994531f, m);
            atomicAdd(&g_cnt[bin], 1.0);
            atomicAdd(&g_sum[bin], (double)bce);
        }
    }
    __syncthreads();

    // Tree-reduce 256 columns x 10 bins, then one atomic pair per bin.
    for (int off = TPB / 2; off > 0; off >>= 1) {
        if (tid < off) {
#pragma unroll
            for (int b = 0; b < BINS; b++) {
                float2 a = hist[b][tid];
                float2 c = hist[b][tid + off];
                hist[b][tid] = make_float2(a.x + c.x, a.y + c.y);
            }
        }
        __syncthreads();
    }

    if (tid < BINS) {
        atomicAdd(&g_cnt[tid], (double)hist[tid][0].x);
        atomicAdd(&g_sum[tid], (double)hist[tid][0].y);
    }
}

// FINALIZE kernel: runs after ghm_main (stream-ordered). Computes the loss
// and resets the accumulators for the next graph replay.
__global__ void ghm_final(float* __restrict__ out)
{
    if (threadIdx.x == 0) {
        double cnt[BINS], sum[BINS];
        double nonempty = 0.0;
        for (int b = 0; b < BINS; b++) {
            cnt[b] = g_cnt[b];
            sum[b] = g_sum[b];
            if (cnt[b] > 0.0) nonempty += 1.0;
        }
        // mean(weight*bce) = (1/N) * sum_b (N/gd_b) * S_b = sum_b S_b / gd_b
        double loss = 0.0;
        for (int b = 0; b < BINS; b++) {
            double gd = cnt[b] * nonempty;
            if (gd < 1e-4) gd = 1e-4;
            loss += sum[b] / gd;
        }
        out[0] = (float)loss;
        for (int b = 0; b < BINS; b++) { g_cnt[b] = 0.0; g_sum[b] = 0.0; }
    }
}

extern "C" void kernel_launch(void* const* d_in, const int* in_sizes, int n_in,
                              void* d_out, int out_size)
{
    // x: [B,2] float32 (2B elems), target: [B] int32 (B elems) — identify by count.
    const float* x;
    const int*   t;
    int nrows;
    if (in_sizes[0] >= 2 * in_sizes[1]) {
        x = (const float*)d_in[0];
        t = (const int*)d_in[1];
        nrows = in_sizes[1];
    } else {
        x = (const float*)d_in[1];
        t = (const int*)d_in[0];
        nrows = in_sizes[0];
    }
    int npairs = nrows >> 1;   // 2 rows (4 elements) per iteration

    ghm_main<<<GRID, TPB>>>((const float4*)x, (const int2*)t, npairs, nrows, x, t);
    ghm_final<<<1, 32>>>((float*)d_out);
}

// round 14
// speedup vs baseline: 1.4393x; 1.1408x over previous
#include <cuda_runtime.h>

#define BINS 10
#define TPB  256
#define BPSM 8
#define GRID (152 * BPSM)   // 8 blocks/SM -> 64 warps/SM

// Global scratch (allocation-free __device__ globals, zero-init at load;
// the finalize kernel re-zeros them so graph replays stay deterministic).
__device__ double g_cnt[BINS];
__device__ double g_sum[BINS];

__device__ __forceinline__ float rcp_fast(float x) { float r; asm("rcp.approx.f32 %0, %1;" : "=f"(r) : "f"(x)); return r; }
__device__ __forceinline__ float lg2_fast(float x) { float r; asm("lg2.approx.f32 %0, %1;" : "=f"(r) : "f"(x)); return r; }
__device__ __forceinline__ float ex2_fast(float x) { float r; asm("ex2.approx.f32 %0, %1;" : "=f"(r) : "f"(x)); return r; }

// s = x ^ mask (mask = target-match << 31);  |s| = |x|
//   e = exp(-|x|);  d = 1+e;  u = 9.9999*rcp(d)
//   us = (s>=0) ? u : 9.9999-u;  bin = trunc(us) in [0,9]
//   bce = (s>=0 ? |x| : 0) + ln2*lg2(d)
__device__ __forceinline__ void ghm_elem(float x, unsigned mask, float2 (*hist)[TPB], int tid)
{
    int   sx = __float_as_int(x) ^ (int)mask;
    float ax = fabsf(x);
    float e  = ex2_fast(ax * -1.4426950408889634f);
    float d  = 1.0f + e;
    float u  = rcp_fast(d) * 9.9999f;
    bool pos = (sx >= 0);
    float us = pos ? u : (9.9999f - u);
    int  bin = (int)us;
    float m  = pos ? ax : 0.0f;
    float bce = fmaf(lg2_fast(d), 0.69314718055994531f, m);
    float2 h = hist[bin][tid];
    h.x += 1.0f;
    h.y += bce;
    hist[bin][tid] = h;
}

// MAIN kernel: streaming histogram only (identical to R13's best).
__global__ void __launch_bounds__(TPB, BPSM)
ghm_main(const float4* __restrict__ x4,
         const int2*   __restrict__ t2,
         int npairs, int nrows,
         const float* __restrict__ xs,
         const int*   __restrict__ ts)
{
    // Single privatized histogram: hist[bin][tid], float2 = (count, bce_sum).
    // Stride 8B -> bank = tid (mod 32): conflict-free for any bin mix.
    __shared__ float2 hist[BINS][TPB];
    const int tid = threadIdx.x;
#pragma unroll
    for (int b = 0; b < BINS; b++) hist[b][tid] = make_float2(0.0f, 0.0f);
    __syncthreads();

    const int stride = GRID * TPB;
    for (int i = blockIdx.x * TPB + tid; i < npairs; i += stride) {
        float4 xv = x4[i];   // rows 2i (x,y) and 2i+1 (z,w)
        int2   tv = t2[i];

        unsigned m1a = ((unsigned)tv.x) << 31, m0a = m1a ^ 0x80000000u;
        unsigned m1b = ((unsigned)tv.y) << 31, m0b = m1b ^ 0x80000000u;

        ghm_elem(xv.x, m0a, hist, tid);
        ghm_elem(xv.y, m1a, hist, tid);
        ghm_elem(xv.z, m0b, hist, tid);
        ghm_elem(xv.w, m1b, hist, tid);
    }

    // Tail row (nrows odd): one thread, direct double atomics.
    if (blockIdx.x == 0 && tid == 0 && (nrows & 1)) {
        int rowi = nrows - 1;
        int t = ts[rowi];
        for (int c = 0; c < 2; c++) {
            float x = xs[rowi * 2 + c];
            unsigned mask = ((t == c) ? 0x80000000u : 0u);
            int   sx = __float_as_int(x) ^ (int)mask;
            float ax = fabsf(x);
            float e  = ex2_fast(ax * -1.4426950408889634f);
            float d  = 1.0f + e;
            float u  = rcp_fast(d) * 9.9999f;
            bool pos = (sx >= 0);
            float us = pos ? u : (9.9999f - u);
            int  bin = (int)us;
            float m  = pos ? ax : 0.0f;
            float bce = fmaf(lg2_fast(d), 0.69314718055994531f, m);
            atomicAdd(&g_cnt[bin], 1.0);
            atomicAdd(&g_sum[bin], (double)bce);
        }
    }
    __syncthreads();

    // Tree-reduce 256 columns x 10 bins, then one atomic pair per bin.
    for (int off = TPB / 2; off > 0; off >>= 1) {
        if (tid < off) {
#pragma unroll
            for (int b = 0; b < BINS; b++) {
                float2 a = hist[b][tid];
                float2 c = hist[b][tid + off];
                hist[b][tid] = make_float2(a.x + c.x, a.y + c.y);
            }
        }
        __syncthreads();
    }

    if (tid < BINS) {
        atomicAdd(&g_cnt[tid], (double)hist[tid][0].x);
        atomicAdd(&g_sum[tid], (double)hist[tid][0].y);
    }
}

// FINALIZE kernel, PARALLELIZED: thread b owns bin b. All 20 global loads
// issue in parallel (one latency exposure instead of twenty serial ones),
// per-bin DP divide in parallel, warp-shuffle reduction, parallel reset.
__global__ void ghm_final(float* __restrict__ out)
{
    const int tid = threadIdx.x;
    double cnt = 0.0, sum = 0.0;
    if (tid < BINS) {
        cnt = g_cnt[tid];
        sum = g_sum[tid];
    }

    unsigned ball = __ballot_sync(0xffffffffu, (tid < BINS) && (cnt > 0.0));
    double nonempty = (double)__popc(ball);

    double term = 0.0;
    if (tid < BINS) {
        double gd = cnt * nonempty;
        if (gd < 1e-4) gd = 1e-4;
        term = sum / gd;   // parallel DP divides
    }

    // Warp reduction (sum of 10 terms; others contribute 0).
#pragma unroll
    for (int off = 16; off > 0; off >>= 1)
        term += __shfl_down_sync(0xffffffffu, term, off);

    if (tid == 0) out[0] = (float)term;

    // Reset for the next graph replay (parallel).
    if (tid < BINS) {
        g_cnt[tid] = 0.0;
        g_sum[tid] = 0.0;
    }
}

extern "C" void kernel_launch(void* const* d_in, const int* in_sizes, int n_in,
                              void* d_out, int out_size)
{
    // x: [B,2] float32 (2B elems), target: [B] int32 (B elems) — identify by count.
    const float* x;
    const int*   t;
    int nrows;
    if (in_sizes[0] >= 2 * in_sizes[1]) {
        x = (const float*)d_in[0];
        t = (const int*)d_in[1];
        nrows = in_sizes[1];
    } else {
        x = (const float*)d_in[1];
        t = (const int*)d_in[0];
        nrows = in_sizes[0];
    }
    int npairs = nrows >> 1;   // 2 rows (4 elements) per iteration

    ghm_main<<<GRID, TPB>>>((const float4*)x, (const int2*)t, npairs, nrows, x, t);
    ghm_final<<<1, 32>>>((float*)d_out);
}